// round 1
// baseline (speedup 1.0000x reference)
#include <cuda_runtime.h>
#include <math.h>

#define D     256
#define NMAX  8192
#define BM    128
#define BN    128
#define BK    16
#define TM    8
#define TN    8
#define INVT  20.0f   // 1 / 0.05

// Scratch (allocation-free rule: __device__ globals)
__device__ float g_En[NMAX * D];
__device__ float g_Pn[NMAX * D];
__device__ float g_Nn[NMAX * D];
__device__ float g_spos[NMAX];
__device__ float g_rs1[NMAX];
__device__ float g_rs2[NMAX];

// ---------------------------------------------------------------------------
// Block-wide sum reduction with broadcast (256 threads).
// ---------------------------------------------------------------------------
__device__ __forceinline__ float block_reduce_bcast(float v) {
    __shared__ float sh[32];
    const int lane = threadIdx.x & 31;
    const int w    = threadIdx.x >> 5;
    #pragma unroll
    for (int o = 16; o > 0; o >>= 1)
        v += __shfl_xor_sync(0xffffffffu, v, o);
    if (lane == 0) sh[w] = v;
    __syncthreads();
    if (w == 0) {
        int nwarps = (blockDim.x + 31) >> 5;
        float r = (lane < nwarps) ? sh[lane] : 0.0f;
        #pragma unroll
        for (int o = 16; o > 0; o >>= 1)
            r += __shfl_xor_sync(0xffffffffu, r, o);
        if (lane == 0) sh[0] = r;
    }
    __syncthreads();
    float out = sh[0];
    __syncthreads();   // safe reuse of sh on subsequent calls
    return out;
}

// ---------------------------------------------------------------------------
// Kernel 1: row-normalize the three matrices; spos[i] = dot(e_hat_i, p_hat_i).
// One block per row, 256 threads == D.
// ---------------------------------------------------------------------------
__global__ void normalize_kernel(const float* __restrict__ e,
                                 const float* __restrict__ p,
                                 const float* __restrict__ nn) {
    const int row = blockIdx.x;
    const int t   = threadIdx.x;
    const size_t idx = (size_t)row * D + t;

    float ve = e[idx], vp = p[idx], vn = nn[idx];

    float se = block_reduce_bcast(ve * ve);
    float sp = block_reduce_bcast(vp * vp);
    float sn = block_reduce_bcast(vn * vn);

    float ne = ve / fmaxf(sqrtf(se), 1e-8f);
    float np = vp / fmaxf(sqrtf(sp), 1e-8f);
    float nv = vn / fmaxf(sqrtf(sn), 1e-8f);

    g_En[idx] = ne;
    g_Pn[idx] = np;
    g_Nn[idx] = nv;

    float dsum = block_reduce_bcast(ne * np);
    if (t == 0) g_spos[row] = dsum;
}

// ---------------------------------------------------------------------------
// Kernel 2: fused GEMM + exp row-sum.
//   rs[i] = sum_j exp(INVT * dot(A_i, B_j))
// Grid: 2 * (N/BM) blocks. First half: A=En, B=Nn -> rs1. Second: A=Pn, B=En -> rs2.
// Each block owns BM rows and loops over ALL N columns, so row sums need no atomics.
// 128x128 tile, 8x8 per-thread micro-tile, BK=16, double-buffered smem,
// smem stored K-major ([BK][BM]) for conflict-light vectorized LDS.
// ---------------------------------------------------------------------------
__global__ void __launch_bounds__(256, 1) gemm_expsum_kernel(int N) {
    const int nb  = N / BM;
    const int mat = blockIdx.x / nb;
    const int bm  = blockIdx.x % nb;

    const float* __restrict__ A = mat ? g_Pn : g_En;
    const float* __restrict__ B = mat ? g_En : g_Nn;
    float* __restrict__ rs      = mat ? g_rs2 : g_rs1;

    __shared__ float As[2][BK][BM];
    __shared__ float Bs[2][BK][BN];

    const int tid  = threadIdx.x;
    const int tx   = tid & 15;   // column group (TN*tx)
    const int ty   = tid >> 4;   // row group (TM*ty)
    const int row0 = bm * BM;

    // loader mapping: 512 float4 per (A or B) chunk, 256 threads x 2
    const int lrow = tid >> 2;         // 0..63
    const int lkv  = (tid & 3) << 2;   // 0,4,8,12

    float rowAcc[TM];
    #pragma unroll
    for (int i = 0; i < TM; i++) rowAcc[i] = 0.0f;

    const int NK = D / BK;  // 16 K-chunks

    for (int j0 = 0; j0 < N; j0 += BN) {
        float acc[TM][TN];
        #pragma unroll
        for (int m = 0; m < TM; m++)
            #pragma unroll
            for (int n = 0; n < TN; n++) acc[m][n] = 0.0f;

        float4 aReg[2], bReg[2];

        // prologue: chunk 0 -> buffer 0
        #pragma unroll
        for (int i = 0; i < 2; i++) {
            int r = lrow + i * 64;
            aReg[i] = *(const float4*)&A[(size_t)(row0 + r) * D + lkv];
            bReg[i] = *(const float4*)&B[(size_t)(j0 + r) * D + lkv];
        }
        #pragma unroll
        for (int i = 0; i < 2; i++) {
            int r = lrow + i * 64;
            As[0][lkv + 0][r] = aReg[i].x;  As[0][lkv + 1][r] = aReg[i].y;
            As[0][lkv + 2][r] = aReg[i].z;  As[0][lkv + 3][r] = aReg[i].w;
            Bs[0][lkv + 0][r] = bReg[i].x;  Bs[0][lkv + 1][r] = bReg[i].y;
            Bs[0][lkv + 2][r] = bReg[i].z;  Bs[0][lkv + 3][r] = bReg[i].w;
        }
        __syncthreads();

        int buf = 0;
        for (int kc = 0; kc < NK; kc++) {
            if (kc + 1 < NK) {
                const int k0n = (kc + 1) * BK;
                #pragma unroll
                for (int i = 0; i < 2; i++) {
                    int r = lrow + i * 64;
                    aReg[i] = *(const float4*)&A[(size_t)(row0 + r) * D + k0n + lkv];
                    bReg[i] = *(const float4*)&B[(size_t)(j0 + r) * D + k0n + lkv];
                }
            }

            #pragma unroll
            for (int kk = 0; kk < BK; kk++) {
                float4 a0 = *(const float4*)&As[buf][kk][ty * TM];
                float4 a1 = *(const float4*)&As[buf][kk][ty * TM + 4];
                float4 b0 = *(const float4*)&Bs[buf][kk][tx * TN];
                float4 b1 = *(const float4*)&Bs[buf][kk][tx * TN + 4];
                float a[TM] = {a0.x, a0.y, a0.z, a0.w, a1.x, a1.y, a1.z, a1.w};
                float b[TN] = {b0.x, b0.y, b0.z, b0.w, b1.x, b1.y, b1.z, b1.w};
                #pragma unroll
                for (int m = 0; m < TM; m++)
                    #pragma unroll
                    for (int n = 0; n < TN; n++)
                        acc[m][n] = fmaf(a[m], b[n], acc[m][n]);
            }

            if (kc + 1 < NK) {
                #pragma unroll
                for (int i = 0; i < 2; i++) {
                    int r = lrow + i * 64;
                    As[buf ^ 1][lkv + 0][r] = aReg[i].x;  As[buf ^ 1][lkv + 1][r] = aReg[i].y;
                    As[buf ^ 1][lkv + 2][r] = aReg[i].z;  As[buf ^ 1][lkv + 3][r] = aReg[i].w;
                    Bs[buf ^ 1][lkv + 0][r] = bReg[i].x;  Bs[buf ^ 1][lkv + 1][r] = bReg[i].y;
                    Bs[buf ^ 1][lkv + 2][r] = bReg[i].z;  Bs[buf ^ 1][lkv + 3][r] = bReg[i].w;
                }
            }
            __syncthreads();
            buf ^= 1;
        }

        // epilogue: exp + row accumulation (args bounded by |cos|/T <= 20 -> fp32 safe)
        #pragma unroll
        for (int m = 0; m < TM; m++) {
            float s = 0.0f;
            #pragma unroll
            for (int n = 0; n < TN; n++)
                s += __expf(INVT * acc[m][n]);
            rowAcc[m] += s;
        }
    }

    // reduce rowAcc across the 16 tx-threads per row (reuse As as scratch)
    __syncthreads();
    float* red = &As[0][0][0];   // 128 rows x 16 partials = 2048 floats, fits
    #pragma unroll
    for (int m = 0; m < TM; m++)
        red[(ty * TM + m) * 16 + tx] = rowAcc[m];
    __syncthreads();
    if (tid < BM) {
        float s = 0.0f;
        #pragma unroll
        for (int i = 0; i < 16; i++) s += red[tid * 16 + i];
        rs[row0 + tid] = s;
    }
}

// ---------------------------------------------------------------------------
// Kernel 3: assemble the scalar loss.
//   lse1_i = log(1 + exp(-spos_i/T) * rs1_i)
//   lse2_i = log(rs2_i) - spos_i/T
//   loss   = mean(lse1) + mean(lse2)
// ---------------------------------------------------------------------------
__global__ void finalize_kernel(float* __restrict__ out, int N) {
    float s = 0.0f;
    for (int i = threadIdx.x; i < N; i += blockDim.x) {
        float sp = g_spos[i] * INVT;
        float t1 = log1pf(__expf(-sp) * g_rs1[i]);
        float t2 = logf(g_rs2[i]) - sp;
        s += t1 + t2;
    }
    s = block_reduce_bcast(s);
    if (threadIdx.x == 0) out[0] = s / (float)N;
}

// ---------------------------------------------------------------------------
extern "C" void kernel_launch(void* const* d_in, const int* in_sizes, int n_in,
                              void* d_out, int out_size) {
    const float* e  = (const float*)d_in[0];
    const float* p  = (const float*)d_in[1];
    const float* nn = (const float*)d_in[2];
    const int N = in_sizes[0] / D;   // 8192

    normalize_kernel<<<N, 256>>>(e, p, nn);
    gemm_expsum_kernel<<<2 * (N / BM), 256>>>(N);
    finalize_kernel<<<1, 256>>>((float*)d_out, N);
}

// round 3
// speedup vs baseline: 7.5574x; 7.5574x over previous
#include <cuda_runtime.h>
#include <cuda_bf16.h>
#include <math.h>
#include <cstdint>

#define D     256
#define NMAX  8192
#define BM    128
#define BN    128
#define INVT  20.0f            // 1 / 0.05
#define ROWB  544              // smem row pitch bytes: 256*2 + 16 pad (conflict-light, 16B aligned)
#define TILE_BYTES (BM * ROWB) // 69632
#define SMEM_TOTAL (2 * TILE_BYTES)

// ---------------------------------------------------------------------------
// Scratch (__device__ globals: allocation-free rule)
// ---------------------------------------------------------------------------
__device__ float g_spos[NMAX];
__device__ float g_rs1[NMAX];
__device__ float g_rs2[NMAX];
__device__ __align__(16) __nv_bfloat16 g_Ebf[NMAX * D];
__device__ __align__(16) __nv_bfloat16 g_Pbf[NMAX * D];
__device__ __align__(16) __nv_bfloat16 g_Nbf[NMAX * D];

__device__ __forceinline__ uint32_t smem_to_u32(const void* p) {
    uint32_t a;
    asm("{ .reg .u64 t; cvta.to.shared.u64 t, %1; cvt.u32.u64 %0, t; }" : "=r"(a) : "l"(p));
    return a;
}

__device__ __forceinline__ void mma16816(float* d, const uint32_t* a, uint32_t b0, uint32_t b1) {
    asm volatile(
        "mma.sync.aligned.m16n8k16.row.col.f32.bf16.bf16.f32 "
        "{%0,%1,%2,%3}, {%4,%5,%6,%7}, {%8,%9}, {%0,%1,%2,%3};"
        : "+f"(d[0]), "+f"(d[1]), "+f"(d[2]), "+f"(d[3])
        : "r"(a[0]), "r"(a[1]), "r"(a[2]), "r"(a[3]), "r"(b0), "r"(b1));
}

// issue one 128x256 bf16 tile (row pitch 512B in gmem) into smem via cp.async
__device__ __forceinline__ void issue_tile(uint32_t sdst, const __nv_bfloat16* src, int tid) {
    #pragma unroll
    for (int i = 0; i < 16; i++) {
        int flat = tid + (i << 8);
        int r = flat >> 5, c = flat & 31;
        uint32_t d = sdst + r * ROWB + c * 16;
        const char* g = (const char*)src + r * 512 + c * 16;
        asm volatile("cp.async.cg.shared.global [%0], [%1], 16;" :: "r"(d), "l"(g));
    }
}

// ---------------------------------------------------------------------------
// Kernel 1: warp-per-row normalize -> bf16 matrices + fp32 spos
// ---------------------------------------------------------------------------
__global__ void normalize_kernel(const float* __restrict__ e,
                                 const float* __restrict__ p,
                                 const float* __restrict__ nn) {
    int row  = (blockIdx.x * blockDim.x + threadIdx.x) >> 5;
    int lane = threadIdx.x & 31;
    size_t base = (size_t)row * D + lane * 8;

    float ve[8], vp[8], vn[8];
    *(float4*)&ve[0] = *(const float4*)(e + base);
    *(float4*)&ve[4] = *(const float4*)(e + base + 4);
    *(float4*)&vp[0] = *(const float4*)(p + base);
    *(float4*)&vp[4] = *(const float4*)(p + base + 4);
    *(float4*)&vn[0] = *(const float4*)(nn + base);
    *(float4*)&vn[4] = *(const float4*)(nn + base + 4);

    float se = 0.f, sp = 0.f, sn = 0.f;
    #pragma unroll
    for (int i = 0; i < 8; i++) { se += ve[i]*ve[i]; sp += vp[i]*vp[i]; sn += vn[i]*vn[i]; }
    #pragma unroll
    for (int o = 16; o > 0; o >>= 1) {
        se += __shfl_xor_sync(0xffffffffu, se, o);
        sp += __shfl_xor_sync(0xffffffffu, sp, o);
        sn += __shfl_xor_sync(0xffffffffu, sn, o);
    }
    float ie = 1.f / fmaxf(sqrtf(se), 1e-8f);
    float ip = 1.f / fmaxf(sqrtf(sp), 1e-8f);
    float iv = 1.f / fmaxf(sqrtf(sn), 1e-8f);

    float dps = 0.f;
    __nv_bfloat162 be[4], bp[4], bn[4];
    #pragma unroll
    for (int i = 0; i < 4; i++) {
        float e0 = ve[2*i]*ie,  e1 = ve[2*i+1]*ie;
        float p0 = vp[2*i]*ip,  p1 = vp[2*i+1]*ip;
        float n0 = vn[2*i]*iv,  n1 = vn[2*i+1]*iv;
        dps += e0*p0 + e1*p1;
        be[i] = __float22bfloat162_rn(make_float2(e0, e1));
        bp[i] = __float22bfloat162_rn(make_float2(p0, p1));
        bn[i] = __float22bfloat162_rn(make_float2(n0, n1));
    }
    *(uint4*)(g_Ebf + base) = *(uint4*)be;
    *(uint4*)(g_Pbf + base) = *(uint4*)bp;
    *(uint4*)(g_Nbf + base) = *(uint4*)bn;

    #pragma unroll
    for (int o = 16; o > 0; o >>= 1) dps += __shfl_xor_sync(0xffffffffu, dps, o);
    if (lane == 0) g_spos[row] = dps;
}

// ---------------------------------------------------------------------------
// Kernel 2: HMMA (mma.sync bf16) GEMM + fused exp row-sum.
// grid = 2*(N/BM). mat 0: rs1[i] = sum_j exp(20 * e_i.n_j); mat 1: rs2 with (p,e).
// 8 warps: 4 in M x 2 in N. Warp tile 32x64. A fragments register-resident
// across the whole column loop; B double-buffered in smem via cp.async.
// ---------------------------------------------------------------------------
__global__ void __launch_bounds__(256, 1) gemm_expsum_mma(int N) {
    extern __shared__ char smem[];
    const uint32_t sbase = smem_to_u32(smem);
    const int tid  = threadIdx.x;
    const int wid  = tid >> 5, lane = tid & 31;

    const int nb  = N / BM;
    const int mat = blockIdx.x / nb;
    const int bm  = blockIdx.x % nb;
    const __nv_bfloat16* A = mat ? g_Pbf : g_Ebf;
    const __nv_bfloat16* B = mat ? g_Ebf : g_Nbf;
    float* rs = mat ? g_rs2 : g_rs1;
    const int row0 = bm * BM;

    const int warpM = (wid & 3) * 32;
    const int warpN = (wid >> 2) * 64;

    // ---- stage A tile (BM x 256) into buf0, then read frags into registers
    {
        const uint4* g = (const uint4*)(A + (size_t)row0 * D);
        #pragma unroll
        for (int i = 0; i < 16; i++) {
            int flat = tid + (i << 8);
            int r = flat >> 5, c = flat & 31;
            *(uint4*)(smem + r * ROWB + c * 16) = g[r * 32 + c];
        }
    }
    __syncthreads();

    uint32_t aF[2][16][4];   // [mtile][kstep][frag regs]
    {
        const int arow = (lane & 7) + ((lane >> 3) & 1) * 8;  // ldmatrix x4 group rows
        const int kb   = (lane >> 4) * 16;
        #pragma unroll
        for (int mt = 0; mt < 2; mt++) {
            uint32_t base = sbase + (uint32_t)(warpM + mt * 16 + arow) * ROWB + kb;
            #pragma unroll
            for (int k = 0; k < 16; k++) {
                asm volatile("ldmatrix.sync.aligned.m8n8.x4.shared.b16 {%0,%1,%2,%3}, [%4];"
                    : "=r"(aF[mt][k][0]), "=r"(aF[mt][k][1]),
                      "=r"(aF[mt][k][2]), "=r"(aF[mt][k][3])
                    : "r"(base + k * 32));
            }
        }
    }
    __syncthreads();

    // ---- B pipeline
    issue_tile(sbase, B, tid);                       // tile 0 -> buf0
    asm volatile("cp.async.commit_group;");
    asm volatile("cp.async.wait_group 0;" ::: "memory");
    __syncthreads();

    const int T = N / BN;
    float rowAcc[4] = {0.f, 0.f, 0.f, 0.f};
    // per-thread B-frag base address components (ldmatrix x4 over 2 n-tiles)
    const uint32_t brow = (lane & 7) + (lane >> 4) * 8;
    const uint32_t bkb  = ((lane >> 3) & 1) * 16;

    for (int j = 0; j < T; j++) {
        const int cur = j & 1, nxt = cur ^ 1;
        if (j + 1 < T) {
            issue_tile(sbase + (uint32_t)nxt * TILE_BYTES, B + (size_t)(j + 1) * BN * D, tid);
            asm volatile("cp.async.commit_group;");
        }

        float acc[2][8][4];
        #pragma unroll
        for (int mt = 0; mt < 2; mt++)
            #pragma unroll
            for (int nt = 0; nt < 8; nt++)
                #pragma unroll
                for (int c = 0; c < 4; c++) acc[mt][nt][c] = 0.f;

        const uint32_t bbase = sbase + (uint32_t)cur * TILE_BYTES
                             + (uint32_t)(warpN + brow) * ROWB + bkb;
        #pragma unroll
        for (int k = 0; k < 16; k++) {
            #pragma unroll
            for (int np = 0; np < 4; np++) {      // n-tile pair: tiles 2np, 2np+1
                uint32_t b0, b1, b2, b3;
                asm volatile("ldmatrix.sync.aligned.m8n8.x4.shared.b16 {%0,%1,%2,%3}, [%4];"
                    : "=r"(b0), "=r"(b1), "=r"(b2), "=r"(b3)
                    : "r"(bbase + (uint32_t)np * 16 * ROWB + (uint32_t)k * 32));
                #pragma unroll
                for (int mt = 0; mt < 2; mt++) {
                    mma16816(acc[mt][2*np],     aF[mt][k], b0, b1);
                    mma16816(acc[mt][2*np + 1], aF[mt][k], b2, b3);
                }
            }
        }

        // fused epilogue: exp + per-row accumulate (cos/T bounded by 20 -> fp32 safe)
        #pragma unroll
        for (int mt = 0; mt < 2; mt++)
            #pragma unroll
            for (int nt = 0; nt < 8; nt++) {
                rowAcc[mt*2+0] += __expf(INVT * acc[mt][nt][0]) + __expf(INVT * acc[mt][nt][1]);
                rowAcc[mt*2+1] += __expf(INVT * acc[mt][nt][2]) + __expf(INVT * acc[mt][nt][3]);
            }

        if (j + 1 < T) asm volatile("cp.async.wait_group 0;" ::: "memory");
        __syncthreads();
    }

    // ---- reduce: lanes with same lane/4 share a row (lane%4 varies)
    #pragma unroll
    for (int i = 0; i < 4; i++) {
        rowAcc[i] += __shfl_xor_sync(0xffffffffu, rowAcc[i], 1);
        rowAcc[i] += __shfl_xor_sync(0xffffffffu, rowAcc[i], 2);
    }
    float* red = (float*)smem;   // 128 rows x 2 warpN partials
    if ((lane & 3) == 0) {
        int rbase = warpM + (lane >> 2);
        int wn = wid >> 2;
        red[(rbase +  0) * 2 + wn] = rowAcc[0];
        red[(rbase +  8) * 2 + wn] = rowAcc[1];
        red[(rbase + 16) * 2 + wn] = rowAcc[2];
        red[(rbase + 24) * 2 + wn] = rowAcc[3];
    }
    __syncthreads();
    if (tid < BM) rs[row0 + tid] = red[tid * 2] + red[tid * 2 + 1];
}

// ---------------------------------------------------------------------------
// Kernel 3: loss = mean[ log1p(exp(-spos/T)*rs1) ] + mean[ log(rs2) - spos/T ]
// ---------------------------------------------------------------------------
__global__ void finalize_kernel(float* __restrict__ out, int N) {
    __shared__ float sh[32];
    float s = 0.f;
    for (int i = threadIdx.x; i < N; i += blockDim.x) {
        float sp = g_spos[i] * INVT;
        s += log1pf(__expf(-sp) * g_rs1[i]) + (logf(g_rs2[i]) - sp);
    }
    int lane = threadIdx.x & 31, w = threadIdx.x >> 5;
    #pragma unroll
    for (int o = 16; o > 0; o >>= 1) s += __shfl_xor_sync(0xffffffffu, s, o);
    if (lane == 0) sh[w] = s;
    __syncthreads();
    if (w == 0) {
        float r = (lane < (int)(blockDim.x >> 5)) ? sh[lane] : 0.f;
        #pragma unroll
        for (int o = 16; o > 0; o >>= 1) r += __shfl_xor_sync(0xffffffffu, r, o);
        if (lane == 0) out[0] = r / (float)N;
    }
}

// ---------------------------------------------------------------------------
extern "C" void kernel_launch(void* const* d_in, const int* in_sizes, int n_in,
                              void* d_out, int out_size) {
    const float* e  = (const float*)d_in[0];
    const float* p  = (const float*)d_in[1];
    const float* nn = (const float*)d_in[2];
    const int N = in_sizes[0] / D;   // 8192

    static bool attr_set = false;
    if (!attr_set) {
        cudaFuncSetAttribute(gemm_expsum_mma, cudaFuncAttributeMaxDynamicSharedMemorySize, SMEM_TOTAL);
        attr_set = true;
    }

    normalize_kernel<<<N / 8, 256>>>(e, p, nn);
    gemm_expsum_mma<<<2 * (N / BM), 256, SMEM_TOTAL>>>(N);
    finalize_kernel<<<1, 1024>>>((float*)d_out, N);
}

// round 4
// speedup vs baseline: 8.9056x; 1.1784x over previous
#include <cuda_runtime.h>
#include <cuda_bf16.h>
#include <math.h>
#include <cstdint>

#define D     256
#define NMAX  8192
#define BM    128
#define BN    128
#define INVT  20.0f            // 1 / 0.05
#define PITCH 512              // smem row pitch (swizzled, conflict-free)
#define TILE_BYTES (BM * PITCH)        // 65536
#define SMEM_TOTAL (2 * TILE_BYTES)    // 131072

// ---------------------------------------------------------------------------
// Scratch (__device__ globals: allocation-free rule)
// ---------------------------------------------------------------------------
__device__ float g_spos[NMAX];
__device__ float g_rs1[NMAX];
__device__ float g_rs2[NMAX];
__device__ __align__(16) __nv_bfloat16 g_Ebf[NMAX * D];
__device__ __align__(16) __nv_bfloat16 g_Pbf[NMAX * D];
__device__ __align__(16) __nv_bfloat16 g_Nbf[NMAX * D];

__device__ __forceinline__ uint32_t smem_to_u32(const void* p) {
    uint32_t a;
    asm("{ .reg .u64 t; cvta.to.shared.u64 t, %1; cvt.u32.u64 %0, t; }" : "=r"(a) : "l"(p));
    return a;
}

// swizzled byte offset for (row, 16B-chunk c16), c16 in 0..31
__device__ __forceinline__ uint32_t off16(uint32_t r, uint32_t c16) {
    return r * PITCH + ((((c16 & 7u) ^ (r & 7u)) | (c16 & 24u)) << 4);
}

__device__ __forceinline__ void mma16816(float* d, const uint32_t* a, uint32_t b0, uint32_t b1) {
    asm volatile(
        "mma.sync.aligned.m16n8k16.row.col.f32.bf16.bf16.f32 "
        "{%0,%1,%2,%3}, {%4,%5,%6,%7}, {%8,%9}, {%0,%1,%2,%3};"
        : "+f"(d[0]), "+f"(d[1]), "+f"(d[2]), "+f"(d[3])
        : "r"(a[0]), "r"(a[1]), "r"(a[2]), "r"(a[3]), "r"(b0), "r"(b1));
}

// issue one 128x256 bf16 tile (gmem row pitch 512B) into swizzled smem via cp.async
__device__ __forceinline__ void issue_tile(uint32_t sdst, const __nv_bfloat16* src, int tid) {
    #pragma unroll
    for (int i = 0; i < 16; i++) {
        int flat = tid + (i << 8);
        uint32_t r = (uint32_t)flat >> 5, c = (uint32_t)flat & 31;
        uint32_t d = sdst + off16(r, c);
        const char* g = (const char*)src + r * 512 + c * 16;
        asm volatile("cp.async.cg.shared.global [%0], [%1], 16;" :: "r"(d), "l"(g));
    }
}

// ---------------------------------------------------------------------------
// Kernel 1: warp-per-row normalize -> bf16 matrices + fp32 spos
// ---------------------------------------------------------------------------
__global__ void normalize_kernel(const float* __restrict__ e,
                                 const float* __restrict__ p,
                                 const float* __restrict__ nn) {
    int row  = (blockIdx.x * blockDim.x + threadIdx.x) >> 5;
    int lane = threadIdx.x & 31;
    size_t base = (size_t)row * D + lane * 8;

    float ve[8], vp[8], vn[8];
    *(float4*)&ve[0] = *(const float4*)(e + base);
    *(float4*)&ve[4] = *(const float4*)(e + base + 4);
    *(float4*)&vp[0] = *(const float4*)(p + base);
    *(float4*)&vp[4] = *(const float4*)(p + base + 4);
    *(float4*)&vn[0] = *(const float4*)(nn + base);
    *(float4*)&vn[4] = *(const float4*)(nn + base + 4);

    float se = 0.f, sp = 0.f, sn = 0.f;
    #pragma unroll
    for (int i = 0; i < 8; i++) { se += ve[i]*ve[i]; sp += vp[i]*vp[i]; sn += vn[i]*vn[i]; }
    #pragma unroll
    for (int o = 16; o > 0; o >>= 1) {
        se += __shfl_xor_sync(0xffffffffu, se, o);
        sp += __shfl_xor_sync(0xffffffffu, sp, o);
        sn += __shfl_xor_sync(0xffffffffu, sn, o);
    }
    float ie = 1.f / fmaxf(sqrtf(se), 1e-8f);
    float ip = 1.f / fmaxf(sqrtf(sp), 1e-8f);
    float iv = 1.f / fmaxf(sqrtf(sn), 1e-8f);

    float dps = 0.f;
    __nv_bfloat162 be[4], bp[4], bn[4];
    #pragma unroll
    for (int i = 0; i < 4; i++) {
        float e0 = ve[2*i]*ie,  e1 = ve[2*i+1]*ie;
        float p0 = vp[2*i]*ip,  p1 = vp[2*i+1]*ip;
        float n0 = vn[2*i]*iv,  n1 = vn[2*i+1]*iv;
        dps += e0*p0 + e1*p1;
        be[i] = __float22bfloat162_rn(make_float2(e0, e1));
        bp[i] = __float22bfloat162_rn(make_float2(p0, p1));
        bn[i] = __float22bfloat162_rn(make_float2(n0, n1));
    }
    *(uint4*)(g_Ebf + base) = *(uint4*)be;
    *(uint4*)(g_Pbf + base) = *(uint4*)bp;
    *(uint4*)(g_Nbf + base) = *(uint4*)bn;

    #pragma unroll
    for (int o = 16; o > 0; o >>= 1) dps += __shfl_xor_sync(0xffffffffu, dps, o);
    if (lane == 0) g_spos[row] = dps;
}

// ---------------------------------------------------------------------------
// Kernel 2: HMMA bf16 GEMM + fused exp row-sum.
// grid = 2*(N/BM). Tile split into two N-halves so the exp epilogue of one
// half overlaps the MMAs of the next (MUFU hidden under tensor pipe).
// Swizzled smem -> conflict-free ldmatrix. A fragments register-resident.
// ---------------------------------------------------------------------------
__global__ void __launch_bounds__(256, 1) gemm_expsum_mma(int N) {
    extern __shared__ char smem[];
    const uint32_t sbase = smem_to_u32(smem);
    const int tid  = threadIdx.x;
    const int wid  = tid >> 5, lane = tid & 31;

    const int nb  = N / BM;
    const int mat = blockIdx.x / nb;
    const int bm  = blockIdx.x % nb;
    const __nv_bfloat16* A = mat ? g_Pbf : g_Ebf;
    const __nv_bfloat16* B = mat ? g_Ebf : g_Nbf;
    float* rs = mat ? g_rs2 : g_rs1;
    const int row0 = bm * BM;

    const int warpM = (wid & 3) * 32;
    const int warpN = (wid >> 2) * 64;

    // ---- stage A tile into buf0 (swizzled), read frags into registers
    {
        const uint4* g = (const uint4*)(A + (size_t)row0 * D);
        #pragma unroll
        for (int i = 0; i < 16; i++) {
            int flat = tid + (i << 8);
            uint32_t r = (uint32_t)flat >> 5, c = (uint32_t)flat & 31;
            *(uint4*)(smem + off16(r, c)) = g[r * 32 + c];
        }
    }
    __syncthreads();

    uint32_t aF[2][16][4];   // [mtile][kstep][frag regs]
    {
        const uint32_t arow = (lane & 7) + ((lane >> 3) & 1) * 8;
        const uint32_t khi  = (uint32_t)(lane >> 4);   // 0/1 -> +16B
        #pragma unroll
        for (int mt = 0; mt < 2; mt++) {
            uint32_t row = (uint32_t)(warpM + mt * 16) + arow;
            #pragma unroll
            for (int k = 0; k < 16; k++) {
                uint32_t addr = sbase + off16(row, 2u * k + khi);
                asm volatile("ldmatrix.sync.aligned.m8n8.x4.shared.b16 {%0,%1,%2,%3}, [%4];"
                    : "=r"(aF[mt][k][0]), "=r"(aF[mt][k][1]),
                      "=r"(aF[mt][k][2]), "=r"(aF[mt][k][3])
                    : "r"(addr));
            }
        }
    }
    __syncthreads();

    // ---- B pipeline
    issue_tile(sbase, B, tid);                       // tile 0 -> buf0
    asm volatile("cp.async.commit_group;");
    asm volatile("cp.async.wait_group 0;" ::: "memory");
    __syncthreads();

    const int T = N / BN;
    float rowAcc[4] = {0.f, 0.f, 0.f, 0.f};
    const uint32_t brow = (lane & 7) + (lane >> 4) * 8;
    const uint32_t bhi  = (uint32_t)((lane >> 3) & 1);

    for (int j = 0; j < T; j++) {
        const int cur = j & 1, nxt = cur ^ 1;
        if (j + 1 < T) {
            issue_tile(sbase + (uint32_t)nxt * TILE_BYTES, B + (size_t)(j + 1) * BN * D, tid);
            asm volatile("cp.async.commit_group;");
        }
        const uint32_t cbase = sbase + (uint32_t)cur * TILE_BYTES;

        #pragma unroll
        for (int half = 0; half < 2; half++) {
            float acc[2][4][4];
            #pragma unroll
            for (int mt = 0; mt < 2; mt++)
                #pragma unroll
                for (int nt = 0; nt < 4; nt++)
                    #pragma unroll
                    for (int c = 0; c < 4; c++) acc[mt][nt][c] = 0.f;

            const uint32_t rowp0 = (uint32_t)(warpN + (half * 2 + 0) * 16) + brow;
            const uint32_t rowp1 = (uint32_t)(warpN + (half * 2 + 1) * 16) + brow;
            #pragma unroll
            for (int k = 0; k < 16; k++) {
                uint32_t c16 = 2u * k + bhi;
                uint32_t b0, b1, b2, b3;
                asm volatile("ldmatrix.sync.aligned.m8n8.x4.shared.b16 {%0,%1,%2,%3}, [%4];"
                    : "=r"(b0), "=r"(b1), "=r"(b2), "=r"(b3)
                    : "r"(cbase + off16(rowp0, c16)));
                #pragma unroll
                for (int mt = 0; mt < 2; mt++) {
                    mma16816(acc[mt][0], aF[mt][k], b0, b1);
                    mma16816(acc[mt][1], aF[mt][k], b2, b3);
                }
                asm volatile("ldmatrix.sync.aligned.m8n8.x4.shared.b16 {%0,%1,%2,%3}, [%4];"
                    : "=r"(b0), "=r"(b1), "=r"(b2), "=r"(b3)
                    : "r"(cbase + off16(rowp1, c16)));
                #pragma unroll
                for (int mt = 0; mt < 2; mt++) {
                    mma16816(acc[mt][2], aF[mt][k], b0, b1);
                    mma16816(acc[mt][3], aF[mt][k], b2, b3);
                }
            }

            // epilogue for this half: independent of next half's MMAs ->
            // MUFU overlaps tensor pipe
            #pragma unroll
            for (int mt = 0; mt < 2; mt++)
                #pragma unroll
                for (int nt = 0; nt < 4; nt++) {
                    rowAcc[mt*2+0] += __expf(INVT * acc[mt][nt][0]) + __expf(INVT * acc[mt][nt][1]);
                    rowAcc[mt*2+1] += __expf(INVT * acc[mt][nt][2]) + __expf(INVT * acc[mt][nt][3]);
                }
        }

        if (j + 1 < T) asm volatile("cp.async.wait_group 0;" ::: "memory");
        __syncthreads();
    }

    // ---- reduce: lane%4 spans a quad sharing rows
    #pragma unroll
    for (int i = 0; i < 4; i++) {
        rowAcc[i] += __shfl_xor_sync(0xffffffffu, rowAcc[i], 1);
        rowAcc[i] += __shfl_xor_sync(0xffffffffu, rowAcc[i], 2);
    }
    float* red = (float*)smem;   // 128 rows x 2 warpN partials
    if ((lane & 3) == 0) {
        int rbase = warpM + (lane >> 2);
        int wn = wid >> 2;
        red[(rbase +  0) * 2 + wn] = rowAcc[0];
        red[(rbase +  8) * 2 + wn] = rowAcc[1];
        red[(rbase + 16) * 2 + wn] = rowAcc[2];
        red[(rbase + 24) * 2 + wn] = rowAcc[3];
    }
    __syncthreads();
    if (tid < BM) rs[row0 + tid] = red[tid * 2] + red[tid * 2 + 1];
}

// ---------------------------------------------------------------------------
// Kernel 3: loss = mean[ log1p(exp(-spos/T)*rs1) ] + mean[ log(rs2) - spos/T ]
// ---------------------------------------------------------------------------
__global__ void finalize_kernel(float* __restrict__ out, int N) {
    __shared__ float sh[32];
    float s = 0.f;
    for (int i = threadIdx.x; i < N; i += blockDim.x) {
        float sp = g_spos[i] * INVT;
        s += log1pf(__expf(-sp) * g_rs1[i]) + (logf(g_rs2[i]) - sp);
    }
    int lane = threadIdx.x & 31, w = threadIdx.x >> 5;
    #pragma unroll
    for (int o = 16; o > 0; o >>= 1) s += __shfl_xor_sync(0xffffffffu, s, o);
    if (lane == 0) sh[w] = s;
    __syncthreads();
    if (w == 0) {
        float r = (lane < (int)(blockDim.x >> 5)) ? sh[lane] : 0.f;
        #pragma unroll
        for (int o = 16; o > 0; o >>= 1) r += __shfl_xor_sync(0xffffffffu, r, o);
        if (lane == 0) out[0] = r / (float)N;
    }
}

// ---------------------------------------------------------------------------
extern "C" void kernel_launch(void* const* d_in, const int* in_sizes, int n_in,
                              void* d_out, int out_size) {
    const float* e  = (const float*)d_in[0];
    const float* p  = (const float*)d_in[1];
    const float* nn = (const float*)d_in[2];
    const int N = in_sizes[0] / D;   // 8192

    static bool attr_set = false;
    if (!attr_set) {
        cudaFuncSetAttribute(gemm_expsum_mma, cudaFuncAttributeMaxDynamicSharedMemorySize, SMEM_TOTAL);
        attr_set = true;
    }

    normalize_kernel<<<N / 8, 256>>>(e, p, nn);
    gemm_expsum_mma<<<2 * (N / BM), 256, SMEM_TOTAL>>>(N);
    finalize_kernel<<<1, 1024>>>((float*)d_out, N);
}

// round 5
// speedup vs baseline: 9.5412x; 1.0714x over previous
#include <cuda_runtime.h>
#include <cuda_bf16.h>
#include <math.h>
#include <cstdint>

#define D     256
#define NMAX  8192
#define BM    128
#define BN    128
#define NB    (NMAX / BM)     // 64 m-blocks per matrix
#define NT    (NMAX / BN)     // 64 j-tiles per m-block
#define TOTAL_TILES (2 * NB * NT)   // 8192
#define GRID_GEMM 148
#define INVT  20.0f            // 1 / 0.05
#define PITCH 512              // smem row pitch (swizzled, conflict-free)
#define TILE_BYTES (BM * PITCH)        // 65536
#define SMEM_TOTAL (2 * TILE_BYTES)    // 131072

// ---------------------------------------------------------------------------
// Scratch (__device__ globals: allocation-free rule)
// ---------------------------------------------------------------------------
__device__ float g_spos[NMAX];
__device__ float g_rs1[NMAX];
__device__ float g_rs2[NMAX];
__device__ __align__(16) __nv_bfloat16 g_Ebf[NMAX * D];
__device__ __align__(16) __nv_bfloat16 g_Pbf[NMAX * D];
__device__ __align__(16) __nv_bfloat16 g_Nbf[NMAX * D];

__device__ __forceinline__ uint32_t smem_to_u32(const void* p) {
    uint32_t a;
    asm("{ .reg .u64 t; cvta.to.shared.u64 t, %1; cvt.u32.u64 %0, t; }" : "=r"(a) : "l"(p));
    return a;
}

// swizzled byte offset for (row, 16B-chunk c16), c16 in 0..31
__device__ __forceinline__ uint32_t off16(uint32_t r, uint32_t c16) {
    return r * PITCH + ((((c16 & 7u) ^ (r & 7u)) | (c16 & 24u)) << 4);
}

__device__ __forceinline__ void mma16816(float* d, const uint32_t* a, uint32_t b0, uint32_t b1) {
    asm volatile(
        "mma.sync.aligned.m16n8k16.row.col.f32.bf16.bf16.f32 "
        "{%0,%1,%2,%3}, {%4,%5,%6,%7}, {%8,%9}, {%0,%1,%2,%3};"
        : "+f"(d[0]), "+f"(d[1]), "+f"(d[2]), "+f"(d[3])
        : "r"(a[0]), "r"(a[1]), "r"(a[2]), "r"(a[3]), "r"(b0), "r"(b1));
}

// issue one 128x256 bf16 tile (gmem row pitch 512B) into swizzled smem via cp.async
__device__ __forceinline__ void issue_tile(uint32_t sdst, const __nv_bfloat16* src, int tid) {
    #pragma unroll
    for (int i = 0; i < 16; i++) {
        int flat = tid + (i << 8);
        uint32_t r = (uint32_t)flat >> 5, c = (uint32_t)flat & 31;
        uint32_t d = sdst + off16(r, c);
        const char* g = (const char*)src + r * 512 + c * 16;
        asm volatile("cp.async.cg.shared.global [%0], [%1], 16;" :: "r"(d), "l"(g));
    }
}

// ---------------------------------------------------------------------------
// Kernel 0: zero the row-sum accumulators (atomicAdd targets)
// ---------------------------------------------------------------------------
__global__ void zero_rs() {
    int i = blockIdx.x * blockDim.x + threadIdx.x;
    if (i < NMAX) { g_rs1[i] = 0.f; g_rs2[i] = 0.f; }
}

// ---------------------------------------------------------------------------
// Kernel 1: normalize, 2 rows per warp (doubled MLP) -> bf16 + fp32 spos
// ---------------------------------------------------------------------------
__global__ void normalize_kernel(const float* __restrict__ e,
                                 const float* __restrict__ p,
                                 const float* __restrict__ nn) {
    int warp = (blockIdx.x * blockDim.x + threadIdx.x) >> 5;
    int lane = threadIdx.x & 31;
    int row0 = warp * 2;

    float ve[2][8], vp[2][8], vn[2][8];
    #pragma unroll
    for (int rr = 0; rr < 2; rr++) {
        size_t base = (size_t)(row0 + rr) * D + lane * 8;
        *(float4*)&ve[rr][0] = *(const float4*)(e + base);
        *(float4*)&ve[rr][4] = *(const float4*)(e + base + 4);
        *(float4*)&vp[rr][0] = *(const float4*)(p + base);
        *(float4*)&vp[rr][4] = *(const float4*)(p + base + 4);
        *(float4*)&vn[rr][0] = *(const float4*)(nn + base);
        *(float4*)&vn[rr][4] = *(const float4*)(nn + base + 4);
    }

    float se[2] = {0.f, 0.f}, sp[2] = {0.f, 0.f}, sn[2] = {0.f, 0.f};
    #pragma unroll
    for (int rr = 0; rr < 2; rr++)
        #pragma unroll
        for (int i = 0; i < 8; i++) {
            se[rr] += ve[rr][i]*ve[rr][i];
            sp[rr] += vp[rr][i]*vp[rr][i];
            sn[rr] += vn[rr][i]*vn[rr][i];
        }
    #pragma unroll
    for (int o = 16; o > 0; o >>= 1)
        #pragma unroll
        for (int rr = 0; rr < 2; rr++) {
            se[rr] += __shfl_xor_sync(0xffffffffu, se[rr], o);
            sp[rr] += __shfl_xor_sync(0xffffffffu, sp[rr], o);
            sn[rr] += __shfl_xor_sync(0xffffffffu, sn[rr], o);
        }

    float dps[2];
    #pragma unroll
    for (int rr = 0; rr < 2; rr++) {
        float ie = 1.f / fmaxf(sqrtf(se[rr]), 1e-8f);
        float ip = 1.f / fmaxf(sqrtf(sp[rr]), 1e-8f);
        float iv = 1.f / fmaxf(sqrtf(sn[rr]), 1e-8f);
        float d = 0.f;
        __nv_bfloat162 be[4], bp[4], bn[4];
        #pragma unroll
        for (int i = 0; i < 4; i++) {
            float e0 = ve[rr][2*i]*ie,  e1 = ve[rr][2*i+1]*ie;
            float p0 = vp[rr][2*i]*ip,  p1 = vp[rr][2*i+1]*ip;
            float n0 = vn[rr][2*i]*iv,  n1 = vn[rr][2*i+1]*iv;
            d += e0*p0 + e1*p1;
            be[i] = __float22bfloat162_rn(make_float2(e0, e1));
            bp[i] = __float22bfloat162_rn(make_float2(p0, p1));
            bn[i] = __float22bfloat162_rn(make_float2(n0, n1));
        }
        size_t base = (size_t)(row0 + rr) * D + lane * 8;
        *(uint4*)(g_Ebf + base) = *(uint4*)be;
        *(uint4*)(g_Pbf + base) = *(uint4*)bp;
        *(uint4*)(g_Nbf + base) = *(uint4*)bn;
        dps[rr] = d;
    }
    #pragma unroll
    for (int o = 16; o > 0; o >>= 1) {
        dps[0] += __shfl_xor_sync(0xffffffffu, dps[0], o);
        dps[1] += __shfl_xor_sync(0xffffffffu, dps[1], o);
    }
    if (lane == 0) { g_spos[row0] = dps[0]; g_spos[row0 + 1] = dps[1]; }
}

// ---------------------------------------------------------------------------
// Kernel 2: persistent HMMA GEMM + fused exp row-sum.
// 148 CTAs, each owns a contiguous range of the 8192 (mat, m-block, j-tile)
// jobs. A fragments register-resident per segment; B double-buffered cp.async;
// partial row sums merged via atomicAdd into pre-zeroed g_rs*.
// ---------------------------------------------------------------------------
__global__ void __launch_bounds__(256, 1) gemm_expsum_mma() {
    extern __shared__ char smem[];
    const uint32_t sbase = smem_to_u32(smem);
    const int tid  = threadIdx.x;
    const int wid  = tid >> 5, lane = tid & 31;

    const int warpM = (wid & 3) * 32;
    const int warpN = (wid >> 2) * 64;

    // ldmatrix per-thread address components
    const uint32_t arow = (lane & 7) + ((lane >> 3) & 1) * 8;
    const uint32_t khi  = (uint32_t)(lane >> 4);
    const uint32_t brow = (lane & 7) + (lane >> 4) * 8;
    const uint32_t bhi  = (uint32_t)((lane >> 3) & 1);

    int t   = (int)(((long long)blockIdx.x * TOTAL_TILES) / GRID_GEMM);
    int end = (int)(((long long)(blockIdx.x + 1) * TOTAL_TILES) / GRID_GEMM);

    while (t < end) {
        const int ab  = t >> 6;               // a-block 0..127
        const int j0  = t & 63;
        const int seg = min(NT - j0, end - t);
        const int j1  = j0 + seg;
        const int mat = ab >> 6;
        const int bm  = ab & (NB - 1);
        const __nv_bfloat16* A = mat ? g_Pbf : g_Ebf;
        const __nv_bfloat16* B = mat ? g_Ebf : g_Nbf;
        float* rs = mat ? g_rs2 : g_rs1;
        const int row0 = bm * BM;

        // ---- stage A tile into buf0 (swizzled), read frags into registers
        {
            const uint4* g = (const uint4*)(A + (size_t)row0 * D);
            #pragma unroll
            for (int i = 0; i < 16; i++) {
                int flat = tid + (i << 8);
                uint32_t r = (uint32_t)flat >> 5, c = (uint32_t)flat & 31;
                *(uint4*)(smem + off16(r, c)) = g[r * 32 + c];
            }
        }
        __syncthreads();

        uint32_t aF[2][16][4];
        #pragma unroll
        for (int mt = 0; mt < 2; mt++) {
            uint32_t row = (uint32_t)(warpM + mt * 16) + arow;
            #pragma unroll
            for (int k = 0; k < 16; k++) {
                uint32_t addr = sbase + off16(row, 2u * k + khi);
                asm volatile("ldmatrix.sync.aligned.m8n8.x4.shared.b16 {%0,%1,%2,%3}, [%4];"
                    : "=r"(aF[mt][k][0]), "=r"(aF[mt][k][1]),
                      "=r"(aF[mt][k][2]), "=r"(aF[mt][k][3])
                    : "r"(addr));
            }
        }
        __syncthreads();

        // ---- B pipeline over [j0, j1)
        issue_tile(sbase, B + (size_t)j0 * BN * D, tid);
        asm volatile("cp.async.commit_group;");
        asm volatile("cp.async.wait_group 0;" ::: "memory");
        __syncthreads();

        float rowAcc[4] = {0.f, 0.f, 0.f, 0.f};

        for (int j = j0; j < j1; j++) {
            const int cur = (j - j0) & 1, nxt = cur ^ 1;
            if (j + 1 < j1) {
                issue_tile(sbase + (uint32_t)nxt * TILE_BYTES, B + (size_t)(j + 1) * BN * D, tid);
                asm volatile("cp.async.commit_group;");
            }
            const uint32_t cbase = sbase + (uint32_t)cur * TILE_BYTES;

            #pragma unroll
            for (int half = 0; half < 2; half++) {
                float acc[2][4][4];
                #pragma unroll
                for (int mt = 0; mt < 2; mt++)
                    #pragma unroll
                    for (int nt = 0; nt < 4; nt++)
                        #pragma unroll
                        for (int c = 0; c < 4; c++) acc[mt][nt][c] = 0.f;

                const uint32_t rowp0 = (uint32_t)(warpN + (half * 2 + 0) * 16) + brow;
                const uint32_t rowp1 = (uint32_t)(warpN + (half * 2 + 1) * 16) + brow;
                #pragma unroll
                for (int k = 0; k < 16; k++) {
                    uint32_t c16 = 2u * k + bhi;
                    uint32_t b0, b1, b2, b3;
                    asm volatile("ldmatrix.sync.aligned.m8n8.x4.shared.b16 {%0,%1,%2,%3}, [%4];"
                        : "=r"(b0), "=r"(b1), "=r"(b2), "=r"(b3)
                        : "r"(cbase + off16(rowp0, c16)));
                    #pragma unroll
                    for (int mt = 0; mt < 2; mt++) {
                        mma16816(acc[mt][0], aF[mt][k], b0, b1);
                        mma16816(acc[mt][1], aF[mt][k], b2, b3);
                    }
                    asm volatile("ldmatrix.sync.aligned.m8n8.x4.shared.b16 {%0,%1,%2,%3}, [%4];"
                        : "=r"(b0), "=r"(b1), "=r"(b2), "=r"(b3)
                        : "r"(cbase + off16(rowp1, c16)));
                    #pragma unroll
                    for (int mt = 0; mt < 2; mt++) {
                        mma16816(acc[mt][2], aF[mt][k], b0, b1);
                        mma16816(acc[mt][3], aF[mt][k], b2, b3);
                    }
                }

                // epilogue for this half overlaps next half's MMAs (MUFU hidden)
                #pragma unroll
                for (int mt = 0; mt < 2; mt++)
                    #pragma unroll
                    for (int nt = 0; nt < 4; nt++) {
                        rowAcc[mt*2+0] += __expf(INVT * acc[mt][nt][0]) + __expf(INVT * acc[mt][nt][1]);
                        rowAcc[mt*2+1] += __expf(INVT * acc[mt][nt][2]) + __expf(INVT * acc[mt][nt][3]);
                    }
            }

            if (j + 1 < j1) asm volatile("cp.async.wait_group 0;" ::: "memory");
            __syncthreads();
        }

        // ---- merge partial row sums (quad lanes share rows)
        #pragma unroll
        for (int i = 0; i < 4; i++) {
            rowAcc[i] += __shfl_xor_sync(0xffffffffu, rowAcc[i], 1);
            rowAcc[i] += __shfl_xor_sync(0xffffffffu, rowAcc[i], 2);
        }
        float* red = (float*)smem;
        if ((lane & 3) == 0) {
            int rbase = warpM + (lane >> 2);
            int wn = wid >> 2;
            red[(rbase +  0) * 2 + wn] = rowAcc[0];
            red[(rbase +  8) * 2 + wn] = rowAcc[1];
            red[(rbase + 16) * 2 + wn] = rowAcc[2];
            red[(rbase + 24) * 2 + wn] = rowAcc[3];
        }
        __syncthreads();
        if (tid < BM) atomicAdd(&rs[row0 + tid], red[tid * 2] + red[tid * 2 + 1]);
        __syncthreads();   // smem safe for next segment

        t += seg;
    }
}

// ---------------------------------------------------------------------------
// Kernel 3: loss = mean[ log1p(exp(-spos/T)*rs1) ] + mean[ log(rs2) - spos/T ]
// ---------------------------------------------------------------------------
__global__ void finalize_kernel(float* __restrict__ out, int N) {
    __shared__ float sh[32];
    float s = 0.f;
    for (int i = threadIdx.x; i < N; i += blockDim.x) {
        float sp = g_spos[i] * INVT;
        s += log1pf(__expf(-sp) * g_rs1[i]) + (logf(g_rs2[i]) - sp);
    }
    int lane = threadIdx.x & 31, w = threadIdx.x >> 5;
    #pragma unroll
    for (int o = 16; o > 0; o >>= 1) s += __shfl_xor_sync(0xffffffffu, s, o);
    if (lane == 0) sh[w] = s;
    __syncthreads();
    if (w == 0) {
        float r = (lane < (int)(blockDim.x >> 5)) ? sh[lane] : 0.f;
        #pragma unroll
        for (int o = 16; o > 0; o >>= 1) r += __shfl_xor_sync(0xffffffffu, r, o);
        if (lane == 0) out[0] = r / (float)N;
    }
}

// ---------------------------------------------------------------------------
extern "C" void kernel_launch(void* const* d_in, const int* in_sizes, int n_in,
                              void* d_out, int out_size) {
    const float* e  = (const float*)d_in[0];
    const float* p  = (const float*)d_in[1];
    const float* nn = (const float*)d_in[2];
    const int N = in_sizes[0] / D;   // 8192

    static bool attr_set = false;
    if (!attr_set) {
        cudaFuncSetAttribute(gemm_expsum_mma, cudaFuncAttributeMaxDynamicSharedMemorySize, SMEM_TOTAL);
        attr_set = true;
    }

    zero_rs<<<(NMAX + 1023) / 1024, 1024>>>();
    normalize_kernel<<<N / 16, 256>>>(e, p, nn);
    gemm_expsum_mma<<<GRID_GEMM, 256, SMEM_TOTAL>>>();
    finalize_kernel<<<1, 1024>>>((float*)d_out, N);
}

// round 6
// speedup vs baseline: 9.9301x; 1.0408x over previous
#include <cuda_runtime.h>
#include <cuda_bf16.h>
#include <math.h>
#include <cstdint>

#define D     256
#define NMAX  8192
#define BM    128
#define BN    128
#define NB    (NMAX / BM)     // 64 m-blocks per matrix
#define NT    (NMAX / BN)     // 64 j-tiles per m-block
#define TOTAL_TILES (2 * NB * NT)   // 8192
#define GRID_GEMM 148
#define INVT  20.0f            // 1 / 0.05
#define PITCH 512              // smem row pitch (swizzled, conflict-free)
#define TILE_BYTES (BM * PITCH)        // 65536
#define SMEM_TOTAL (3 * TILE_BYTES)    // 196608 (3-stage B pipeline)

// ---------------------------------------------------------------------------
// Scratch (__device__ globals: allocation-free rule)
// ---------------------------------------------------------------------------
__device__ float g_spos[NMAX];
__device__ float g_rs1[NMAX];
__device__ float g_rs2[NMAX];
__device__ __align__(16) __nv_bfloat16 g_Ebf[NMAX * D];
__device__ __align__(16) __nv_bfloat16 g_Pbf[NMAX * D];
__device__ __align__(16) __nv_bfloat16 g_Nbf[NMAX * D];

__device__ __forceinline__ uint32_t smem_to_u32(const void* p) {
    uint32_t a;
    asm("{ .reg .u64 t; cvta.to.shared.u64 t, %1; cvt.u32.u64 %0, t; }" : "=r"(a) : "l"(p));
    return a;
}

// swizzled byte offset for (row, 16B-chunk c16), c16 in 0..31
__device__ __forceinline__ uint32_t off16(uint32_t r, uint32_t c16) {
    return r * PITCH + ((((c16 & 7u) ^ (r & 7u)) | (c16 & 24u)) << 4);
}

__device__ __forceinline__ void mma16816(float* d, const uint32_t* a, uint32_t b0, uint32_t b1) {
    asm volatile(
        "mma.sync.aligned.m16n8k16.row.col.f32.bf16.bf16.f32 "
        "{%0,%1,%2,%3}, {%4,%5,%6,%7}, {%8,%9}, {%0,%1,%2,%3};"
        : "+f"(d[0]), "+f"(d[1]), "+f"(d[2]), "+f"(d[3])
        : "r"(a[0]), "r"(a[1]), "r"(a[2]), "r"(a[3]), "r"(b0), "r"(b1));
}

#define LDSM_X4(r, addr) \
    asm volatile("ldmatrix.sync.aligned.m8n8.x4.shared.b16 {%0,%1,%2,%3}, [%4];" \
        : "=r"((r)[0]), "=r"((r)[1]), "=r"((r)[2]), "=r"((r)[3]) : "r"(addr))

// issue one 128x256 bf16 tile (gmem row pitch 512B) into swizzled smem via cp.async
__device__ __forceinline__ void issue_tile(uint32_t sdst, const __nv_bfloat16* src, int tid) {
    #pragma unroll
    for (int i = 0; i < 16; i++) {
        int flat = tid + (i << 8);
        uint32_t r = (uint32_t)flat >> 5, c = (uint32_t)flat & 31;
        uint32_t d = sdst + off16(r, c);
        const char* g = (const char*)src + r * 512 + c * 16;
        asm volatile("cp.async.cg.shared.global [%0], [%1], 16;" :: "r"(d), "l"(g));
    }
}

// ---------------------------------------------------------------------------
// Kernel 1: normalize, 2 rows/warp; also zeroes rs accumulators and d_out.
// ---------------------------------------------------------------------------
__global__ void normalize_kernel(const float* __restrict__ e,
                                 const float* __restrict__ p,
                                 const float* __restrict__ nn,
                                 float* __restrict__ out) {
    int warp = (blockIdx.x * blockDim.x + threadIdx.x) >> 5;
    int lane = threadIdx.x & 31;
    int row0 = warp * 2;

    if (lane < 2) { g_rs1[row0 + lane] = 0.f; g_rs2[row0 + lane] = 0.f; }
    if (blockIdx.x == 0 && threadIdx.x == 0) out[0] = 0.f;

    float ve[2][8], vp[2][8], vn[2][8];
    #pragma unroll
    for (int rr = 0; rr < 2; rr++) {
        size_t base = (size_t)(row0 + rr) * D + lane * 8;
        *(float4*)&ve[rr][0] = *(const float4*)(e + base);
        *(float4*)&ve[rr][4] = *(const float4*)(e + base + 4);
        *(float4*)&vp[rr][0] = *(const float4*)(p + base);
        *(float4*)&vp[rr][4] = *(const float4*)(p + base + 4);
        *(float4*)&vn[rr][0] = *(const float4*)(nn + base);
        *(float4*)&vn[rr][4] = *(const float4*)(nn + base + 4);
    }

    float se[2] = {0.f, 0.f}, sp[2] = {0.f, 0.f}, sn[2] = {0.f, 0.f};
    #pragma unroll
    for (int rr = 0; rr < 2; rr++)
        #pragma unroll
        for (int i = 0; i < 8; i++) {
            se[rr] += ve[rr][i]*ve[rr][i];
            sp[rr] += vp[rr][i]*vp[rr][i];
            sn[rr] += vn[rr][i]*vn[rr][i];
        }
    #pragma unroll
    for (int o = 16; o > 0; o >>= 1)
        #pragma unroll
        for (int rr = 0; rr < 2; rr++) {
            se[rr] += __shfl_xor_sync(0xffffffffu, se[rr], o);
            sp[rr] += __shfl_xor_sync(0xffffffffu, sp[rr], o);
            sn[rr] += __shfl_xor_sync(0xffffffffu, sn[rr], o);
        }

    float dps[2];
    #pragma unroll
    for (int rr = 0; rr < 2; rr++) {
        float ie = 1.f / fmaxf(sqrtf(se[rr]), 1e-8f);
        float ip = 1.f / fmaxf(sqrtf(sp[rr]), 1e-8f);
        float iv = 1.f / fmaxf(sqrtf(sn[rr]), 1e-8f);
        float d = 0.f;
        __nv_bfloat162 be[4], bp[4], bn[4];
        #pragma unroll
        for (int i = 0; i < 4; i++) {
            float e0 = ve[rr][2*i]*ie,  e1 = ve[rr][2*i+1]*ie;
            float p0 = vp[rr][2*i]*ip,  p1 = vp[rr][2*i+1]*ip;
            float n0 = vn[rr][2*i]*iv,  n1 = vn[rr][2*i+1]*iv;
            d += e0*p0 + e1*p1;
            be[i] = __float22bfloat162_rn(make_float2(e0, e1));
            bp[i] = __float22bfloat162_rn(make_float2(p0, p1));
            bn[i] = __float22bfloat162_rn(make_float2(n0, n1));
        }
        size_t base = (size_t)(row0 + rr) * D + lane * 8;
        *(uint4*)(g_Ebf + base) = *(uint4*)be;
        *(uint4*)(g_Pbf + base) = *(uint4*)bp;
        *(uint4*)(g_Nbf + base) = *(uint4*)bn;
        dps[rr] = d;
    }
    #pragma unroll
    for (int o = 16; o > 0; o >>= 1) {
        dps[0] += __shfl_xor_sync(0xffffffffu, dps[0], o);
        dps[1] += __shfl_xor_sync(0xffffffffu, dps[1], o);
    }
    if (lane == 0) { g_spos[row0] = dps[0]; g_spos[row0 + 1] = dps[1]; }
}

// ---------------------------------------------------------------------------
// Kernel 2: persistent HMMA GEMM + fused exp row-sum.
// 148 CTAs over 8192 (mat, m-block, j-tile) jobs, contiguous ranges.
// A frags register-resident; B 3-stage cp.async; B ldmatrix software-pipelined;
// per-half epilogue overlaps next half's MMAs; atomicAdd row-sum merge.
// ---------------------------------------------------------------------------
__global__ void __launch_bounds__(256, 1) gemm_expsum_mma() {
    extern __shared__ char smem[];
    const uint32_t sbase = smem_to_u32(smem);
    const int tid  = threadIdx.x;
    const int wid  = tid >> 5, lane = tid & 31;

    const int warpM = (wid & 3) * 32;
    const int warpN = (wid >> 2) * 64;

    const uint32_t arow = (lane & 7) + ((lane >> 3) & 1) * 8;
    const uint32_t khi  = (uint32_t)(lane >> 4);
    const uint32_t brow = (lane & 7) + (lane >> 4) * 8;
    const uint32_t bhi  = (uint32_t)((lane >> 3) & 1);

    int t   = (int)(((long long)blockIdx.x * TOTAL_TILES) / GRID_GEMM);
    int end = (int)(((long long)(blockIdx.x + 1) * TOTAL_TILES) / GRID_GEMM);

    while (t < end) {
        const int ab  = t >> 6;
        const int j0  = t & 63;
        const int seg = min(NT - j0, end - t);
        const int j1  = j0 + seg;
        const int mat = ab >> 6;
        const int bm  = ab & (NB - 1);
        const __nv_bfloat16* A = mat ? g_Pbf : g_Ebf;
        const __nv_bfloat16* B = mat ? g_Ebf : g_Nbf;
        float* rs = mat ? g_rs2 : g_rs1;
        const int row0 = bm * BM;

        // ---- stage A tile into buf0 (swizzled), read frags into registers
        {
            const uint4* g = (const uint4*)(A + (size_t)row0 * D);
            #pragma unroll
            for (int i = 0; i < 16; i++) {
                int flat = tid + (i << 8);
                uint32_t r = (uint32_t)flat >> 5, c = (uint32_t)flat & 31;
                *(uint4*)(smem + off16(r, c)) = g[r * 32 + c];
            }
        }
        __syncthreads();

        uint32_t aF[2][16][4];
        #pragma unroll
        for (int mt = 0; mt < 2; mt++) {
            uint32_t row = (uint32_t)(warpM + mt * 16) + arow;
            #pragma unroll
            for (int k = 0; k < 16; k++)
                LDSM_X4(aF[mt][k], sbase + off16(row, 2u * k + khi));
        }
        __syncthreads();

        // ---- 3-stage B pipeline over [j0, j1)
        issue_tile(sbase, B + (size_t)j0 * BN * D, tid);
        asm volatile("cp.async.commit_group;");
        if (j0 + 1 < j1) {
            issue_tile(sbase + TILE_BYTES, B + (size_t)(j0 + 1) * BN * D, tid);
            asm volatile("cp.async.commit_group;");
        }

        float rowAcc[4] = {0.f, 0.f, 0.f, 0.f};

        for (int j = j0; j < j1; j++) {
            const int sj = j - j0;
            if (j + 2 < j1) {
                issue_tile(sbase + (uint32_t)((sj + 2) % 3) * TILE_BYTES,
                           B + (size_t)(j + 2) * BN * D, tid);
                asm volatile("cp.async.commit_group;");
                asm volatile("cp.async.wait_group 2;" ::: "memory");
            } else if (j + 1 < j1) {
                asm volatile("cp.async.wait_group 1;" ::: "memory");
            } else {
                asm volatile("cp.async.wait_group 0;" ::: "memory");
            }
            __syncthreads();
            const uint32_t cbase = sbase + (uint32_t)(sj % 3) * TILE_BYTES;

            #pragma unroll
            for (int half = 0; half < 2; half++) {
                float acc[2][4][4];
                #pragma unroll
                for (int mt = 0; mt < 2; mt++)
                    #pragma unroll
                    for (int nt = 0; nt < 4; nt++)
                        #pragma unroll
                        for (int c = 0; c < 4; c++) acc[mt][nt][c] = 0.f;

                const uint32_t rowp0 = (uint32_t)(warpN + (half * 2 + 0) * 16) + brow;
                const uint32_t rowp1 = (uint32_t)(warpN + (half * 2 + 1) * 16) + brow;

                // software-pipelined B frags: load k+1 before consuming k
                uint32_t bf[2][8];
                LDSM_X4(&bf[0][0], cbase + off16(rowp0, bhi));
                LDSM_X4(&bf[0][4], cbase + off16(rowp1, bhi));
                #pragma unroll
                for (int k = 0; k < 16; k++) {
                    const int c = k & 1, n = c ^ 1;
                    if (k < 15) {
                        uint32_t c16 = 2u * (k + 1) + bhi;
                        LDSM_X4(&bf[n][0], cbase + off16(rowp0, c16));
                        LDSM_X4(&bf[n][4], cbase + off16(rowp1, c16));
                    }
                    #pragma unroll
                    for (int mt = 0; mt < 2; mt++) {
                        mma16816(acc[mt][0], aF[mt][k], bf[c][0], bf[c][1]);
                        mma16816(acc[mt][1], aF[mt][k], bf[c][2], bf[c][3]);
                        mma16816(acc[mt][2], aF[mt][k], bf[c][4], bf[c][5]);
                        mma16816(acc[mt][3], aF[mt][k], bf[c][6], bf[c][7]);
                    }
                }

                // epilogue for this half overlaps next half's MMAs (MUFU hidden)
                #pragma unroll
                for (int mt = 0; mt < 2; mt++)
                    #pragma unroll
                    for (int nt = 0; nt < 4; nt++) {
                        rowAcc[mt*2+0] += __expf(INVT * acc[mt][nt][0]) + __expf(INVT * acc[mt][nt][1]);
                        rowAcc[mt*2+1] += __expf(INVT * acc[mt][nt][2]) + __expf(INVT * acc[mt][nt][3]);
                    }
            }
            __syncthreads();   // all warps done with buf sj%3 before it is refilled
        }

        // ---- merge partial row sums (quad lanes share rows)
        #pragma unroll
        for (int i = 0; i < 4; i++) {
            rowAcc[i] += __shfl_xor_sync(0xffffffffu, rowAcc[i], 1);
            rowAcc[i] += __shfl_xor_sync(0xffffffffu, rowAcc[i], 2);
        }
        float* red = (float*)smem;
        if ((lane & 3) == 0) {
            int rbase = warpM + (lane >> 2);
            int wn = wid >> 2;
            red[(rbase +  0) * 2 + wn] = rowAcc[0];
            red[(rbase +  8) * 2 + wn] = rowAcc[1];
            red[(rbase + 16) * 2 + wn] = rowAcc[2];
            red[(rbase + 24) * 2 + wn] = rowAcc[3];
        }
        __syncthreads();
        if (tid < BM) atomicAdd(&rs[row0 + tid], red[tid * 2] + red[tid * 2 + 1]);
        __syncthreads();

        t += seg;
    }
}

// ---------------------------------------------------------------------------
// Kernel 3: parallel loss assembly; partial block sums merged via atomicAdd.
//   loss = (1/N) * sum_i[ log1p(exp(-spos/T)*rs1) + log(rs2) - spos/T ]
// ---------------------------------------------------------------------------
__global__ void finalize_kernel(float* __restrict__ out, int N) {
    __shared__ float sh[32];
    int i = blockIdx.x * blockDim.x + threadIdx.x;
    float s = 0.f;
    if (i < N) {
        float sp = g_spos[i] * INVT;
        s = log1pf(__expf(-sp) * g_rs1[i]) + (logf(g_rs2[i]) - sp);
    }
    int lane = threadIdx.x & 31, w = threadIdx.x >> 5;
    #pragma unroll
    for (int o = 16; o > 0; o >>= 1) s += __shfl_xor_sync(0xffffffffu, s, o);
    if (lane == 0) sh[w] = s;
    __syncthreads();
    if (w == 0) {
        float r = (lane < (int)(blockDim.x >> 5)) ? sh[lane] : 0.f;
        #pragma unroll
        for (int o = 16; o > 0; o >>= 1) r += __shfl_xor_sync(0xffffffffu, r, o);
        if (lane == 0) atomicAdd(out, r / (float)N);
    }
}

// ---------------------------------------------------------------------------
extern "C" void kernel_launch(void* const* d_in, const int* in_sizes, int n_in,
                              void* d_out, int out_size) {
    const float* e  = (const float*)d_in[0];
    const float* p  = (const float*)d_in[1];
    const float* nn = (const float*)d_in[2];
    const int N = in_sizes[0] / D;   // 8192

    static bool attr_set = false;
    if (!attr_set) {
        cudaFuncSetAttribute(gemm_expsum_mma, cudaFuncAttributeMaxDynamicSharedMemorySize, SMEM_TOTAL);
        attr_set = true;
    }

    normalize_kernel<<<N / 16, 256>>>(e, p, nn, (float*)d_out);
    gemm_expsum_mma<<<GRID_GEMM, 256, SMEM_TOTAL>>>();
    finalize_kernel<<<N / 1024, 1024>>>((float*)d_out, N);
}